// round 1
// baseline (speedup 1.0000x reference)
#include <cuda_runtime.h>
#include <cstdint>

#define NWARPS 4           // warps per block
#define PAIRS  8           // token pairs per warp tile
#define TOKPT  16          // tokens per warp tile (2*PAIRS)
#define DIMK   32
#define NHEAD  4
#define NMAT   5           // Wv + 4*Wk

struct Smem {
    float  w[NMAT][DIMK][DIMK];          // [mat][d][k]  (transposed weights)
    float  bias[NMAT][DIMK];             // bv, bk[h]
    float  g12[NHEAD][DIMK];             // g1*g2
    float2 emb[NWARPS][PAIRS][DIMK];     // staged embedding pairs
    float2 keyT[NWARPS][NHEAD * PAIRS][DIMK + 1];  // padded -> conflict-free transpose
    float  gate[NWARPS][64];             // [h*16 + t]
};

__device__ __forceinline__ uint64_t pack2(float lo, float hi) {
    uint64_t r; asm("mov.b64 %0,{%1,%2};" : "=l"(r) : "f"(lo), "f"(hi)); return r;
}
__device__ __forceinline__ void unpack2(uint64_t v, float& a, float& b) {
    asm("mov.b64 {%0,%1},%2;" : "=f"(a), "=f"(b) : "l"(v));
}
__device__ __forceinline__ uint64_t ffma2(uint64_t a, uint64_t b, uint64_t c) {
    uint64_t d; asm("fma.rn.f32x2 %0,%1,%2,%3;" : "=l"(d) : "l"(a), "l"(b), "l"(c)); return d;
}
__device__ __forceinline__ uint64_t fmul2(uint64_t a, uint64_t b) {
    uint64_t d; asm("mul.rn.f32x2 %0,%1,%2;" : "=l"(d) : "l"(a), "l"(b)); return d;
}
__device__ __forceinline__ float rsqrt_a(float x){ float r; asm("rsqrt.approx.f32 %0,%1;" : "=f"(r) : "f"(x)); return r; }
__device__ __forceinline__ float sqrt_a (float x){ float r; asm("sqrt.approx.f32 %0,%1;"  : "=f"(r) : "f"(x)); return r; }
__device__ __forceinline__ float ex2_a  (float x){ float r; asm("ex2.approx.f32 %0,%1;"   : "=f"(r) : "f"(x)); return r; }
__device__ __forceinline__ float rcp_a  (float x){ float r; asm("rcp.approx.f32 %0,%1;"   : "=f"(r) : "f"(x)); return r; }

__global__ void __launch_bounds__(NWARPS * 32, 3)
engram_kernel(const float* __restrict__ emb,
              const float* __restrict__ hid,
              const float* __restrict__ Wv,
              const float* __restrict__ bv,
              const float* __restrict__ Wk,
              const float* __restrict__ bk,
              const float* __restrict__ g1,
              const float* __restrict__ g2,
              float* __restrict__ out,
              int ntiles)
{
    extern __shared__ char smem_raw[];
    Smem& s = *reinterpret_cast<Smem*>(smem_raw);

    const int tid  = threadIdx.x;
    const int lane = tid & 31;
    const int warp = tid >> 5;

    // ---- one-time block setup: transpose weights into shared ----
    // Wv [k][d] -> w[0][d][k]
    for (int i = tid; i < DIMK * DIMK; i += blockDim.x) {
        int k = i / DIMK, d = i % DIMK;
        s.w[0][d][k] = Wv[i];
    }
    // Wk [h][k][d] -> w[1+h][d][k]
    for (int i = tid; i < NHEAD * DIMK * DIMK; i += blockDim.x) {
        int h = i / (DIMK * DIMK);
        int k = (i / DIMK) % DIMK;
        int d = i % DIMK;
        s.w[1 + h][d][k] = Wk[i];
    }
    if (tid < DIMK) s.bias[0][tid] = bv[tid];
    for (int i = tid; i < NHEAD * DIMK; i += blockDim.x) {
        s.bias[1 + i / DIMK][i % DIMK] = bk[i];
        s.g12[i / DIMK][i % DIMK] = g1[i] * g2[i];
    }
    __syncthreads();

    const float EPSF   = 1.1920929e-07f;   // float32 eps (torch/jnp default)
    const float INV32  = 0.03125f;
    const float ISQ32  = 0.17677669529663687f;  // 1/sqrt(32)
    const float LOG2E  = 1.4426950408889634f;

    for (int tile = blockIdx.x * NWARPS + warp; tile < ntiles;
         tile += gridDim.x * NWARPS) {

        const int base = tile * TOKPT;

        // ---- stage 16 tokens of emb as packed pairs: emb[w][p][d] = (e_t0[d], e_t1[d]) ----
        const float* embp = emb + (size_t)base * DIMK;
#pragma unroll
        for (int p = 0; p < PAIRS; ++p) {
            float e0 = embp[(2 * p) * DIMK + lane];
            float e1 = embp[(2 * p + 1) * DIMK + lane];
            s.emb[warp][p][lane] = make_float2(e0, e1);
        }
        __syncwarp();

        // ---- accumulators: acc[mat][pair] packs 2 tokens, lane = k ----
        uint64_t acc[NMAT][PAIRS];
#pragma unroll
        for (int m = 0; m < NMAT; ++m) {
            float b = s.bias[m][lane];
            uint64_t b2 = pack2(b, b);
#pragma unroll
            for (int p = 0; p < PAIRS; ++p) acc[m][p] = b2;
        }

        // ---- main GEMV loop over d: 5 matrices x 8 pairs of FFMA2 per d ----
#pragma unroll 8
        for (int d = 0; d < DIMK; ++d) {
            uint64_t wm[NMAT];
#pragma unroll
            for (int m = 0; m < NMAT; ++m) {
                float wv = s.w[m][d][lane];
                wm[m] = pack2(wv, wv);
            }
#pragma unroll
            for (int p = 0; p < PAIRS; ++p) {
                uint64_t e2 = *reinterpret_cast<const uint64_t*>(&s.emb[warp][p][d]);
#pragma unroll
                for (int m = 0; m < NMAT; ++m)
                    acc[m][p] = ffma2(e2, wm[m], acc[m][p]);
            }
        }

        // ---- transpose keys into padded shared (conflict-free) ----
#pragma unroll
        for (int h = 0; h < NHEAD; ++h)
#pragma unroll
            for (int p = 0; p < PAIRS; ++p)
                *reinterpret_cast<uint64_t*>(&s.keyT[warp][h * PAIRS + p][lane]) =
                    acc[1 + h][p];
        __syncwarp();

        // ---- combo phase: lane <-> (head, token); 2 rounds cover 4x16 combos ----
#pragma unroll
        for (int r = 0; r < 2; ++r) {
            int combo = r * 32 + lane;
            int h = combo >> 4;
            int t = combo & 15;
            int p = t >> 1, half = t & 1;
            const float* keyrow =
                reinterpret_cast<const float*>(&s.keyT[warp][h * PAIRS + p][0]) + half;
            const float4* q4 = reinterpret_cast<const float4*>(
                hid + ((size_t)(base + t) * NHEAD + h) * DIMK);

            float kss = 0.f, qss = 0.f, pdot = 0.f;
#pragma unroll
            for (int kk = 0; kk < 8; ++kk) {
                float4 q = q4[kk];
                float kv;
                kv = keyrow[(4 * kk + 0) * 2];
                kss = fmaf(kv, kv, kss); qss = fmaf(q.x, q.x, qss);
                pdot = fmaf(kv * q.x, s.g12[h][4 * kk + 0], pdot);
                kv = keyrow[(4 * kk + 1) * 2];
                kss = fmaf(kv, kv, kss); qss = fmaf(q.y, q.y, qss);
                pdot = fmaf(kv * q.y, s.g12[h][4 * kk + 1], pdot);
                kv = keyrow[(4 * kk + 2) * 2];
                kss = fmaf(kv, kv, kss); qss = fmaf(q.z, q.z, qss);
                pdot = fmaf(kv * q.z, s.g12[h][4 * kk + 2], pdot);
                kv = keyrow[(4 * kk + 3) * 2];
                kss = fmaf(kv, kv, kss); qss = fmaf(q.w, q.w, qss);
                pdot = fmaf(kv * q.w, s.g12[h][4 * kk + 3], pdot);
            }

            float rk = rsqrt_a(fmaf(kss, INV32, EPSF));
            float rq = rsqrt_a(fmaf(qss, INV32, EPSF));
            float gp = pdot * rk * rq * ISQ32;
            float a  = fmaxf(fabsf(gp), 1e-6f);
            float sr = copysignf(sqrt_a(a), gp);
            float ex = ex2_a(-sr * LOG2E);
            float gate = rcp_a(1.f + ex);
            s.gate[warp][combo] = gate;
        }
        __syncwarp();

        // ---- output: out[tok][h][k] = gate[tok][h] * value[tok][k], lane = k ----
        float* outp = out + (size_t)base * (NHEAD * DIMK);
#pragma unroll
        for (int p = 0; p < PAIRS; ++p) {
#pragma unroll
            for (int h = 0; h < NHEAD; ++h) {
                uint64_t g2v =
                    *reinterpret_cast<const uint64_t*>(&s.gate[warp][h * 16 + 2 * p]);
                uint64_t o = fmul2(g2v, acc[0][p]);
                float o0, o1; unpack2(o, o0, o1);
                outp[(2 * p) * (NHEAD * DIMK) + h * DIMK + lane] = o0;
                outp[(2 * p + 1) * (NHEAD * DIMK) + h * DIMK + lane] = o1;
            }
        }
        __syncwarp();   // protect s.gate / s.emb before next tile's writes
    }
}

extern "C" void kernel_launch(void* const* d_in, const int* in_sizes, int n_in,
                              void* d_out, int out_size)
{
    const float* emb = (const float*)d_in[0];
    const float* hid = (const float*)d_in[1];
    const float* Wv  = (const float*)d_in[2];
    const float* bv  = (const float*)d_in[3];
    const float* Wk  = (const float*)d_in[4];
    const float* bk  = (const float*)d_in[5];
    const float* g1  = (const float*)d_in[6];
    const float* g2  = (const float*)d_in[7];

    int ntok   = in_sizes[0] / DIMK;   // B*S
    int ntiles = ntok / TOKPT;         // 16384 for this shape

    size_t smem = sizeof(Smem);
    cudaFuncSetAttribute(engram_kernel,
                         cudaFuncAttributeMaxDynamicSharedMemorySize, (int)smem);

    int blocks = 2048;                 // 8192 warps -> 2 tiles per warp
    engram_kernel<<<blocks, NWARPS * 32, smem>>>(
        emb, hid, Wv, bv, Wk, bk, g1, g2, (float*)d_out, ntiles);
}